// round 8
// baseline (speedup 1.0000x reference)
#include <cuda_runtime.h>
#include <cuda_bf16.h>
#include <cstdint>
#include <math.h>

#define BATCH 256
#define SEQT  128
#define INP   512
#define HID   1024
#define NOUT  32
#define NG    4096   // 4*HID, interleaved gates: n = 4*j + g (0=i,1=f,2=cell,3=o)

// ---------------- scratch (device globals; no cudaMalloc allowed) ----------------
__device__ __nv_bfloat16 g_xt[(size_t)SEQT * BATCH * INP];   // t-major bf16 inputs [t][b][k]
__device__ __nv_bfloat16 g_wi[(size_t)NG * INP];             // packed bf16 input weights
__device__ __nv_bfloat16 g_wh[(size_t)NG * HID];             // packed bf16 hidden weights
__device__ float         g_bias[NG];
__device__ __nv_bfloat16 g_h[2][BATCH * HID];                // double-buffered hidden state
__device__ unsigned      g_barg[2];                          // per-m-group barrier counters

// ---------------- helpers ----------------
__device__ __forceinline__ uint32_t smem_u32(const void* p) {
    return (uint32_t)__cvta_generic_to_shared(p);
}
__device__ __forceinline__ void cp16s(uint32_t dst, const void* src) {
    asm volatile("cp.async.cg.shared.global [%0], [%1], 16;" :: "r"(dst), "l"(src));
}
#define CP_COMMIT() asm volatile("cp.async.commit_group;" ::: "memory")
#define CP_WAIT0()  asm volatile("cp.async.wait_group 0;" ::: "memory")
#define CP_WAIT1()  asm volatile("cp.async.wait_group 1;" ::: "memory")

// 64B-row smem layout (BK=32 bf16), 16B chunk swizzle (R4-proven).
__device__ __forceinline__ uint32_t sw(int row, int c) {
    return (uint32_t)(row * 64 + ((c ^ ((row >> 1) & 3)) << 4));
}
// Persistent Wh smem: 2KB rows (K=1024 bf16), per-row chunk swizzle.
__device__ __forceinline__ uint32_t whsw(int row, int c) {
    return (uint32_t)(row * 2048 + ((c ^ (row & 7)) << 4));
}
// Persistent Wi smem: 1KB rows (K=512 bf16), per-row chunk swizzle.
__device__ __forceinline__ uint32_t wisw(int row, int c) {
    return (uint32_t)(row * 1024 + ((c ^ (row & 7)) << 4));
}

__device__ __forceinline__ void ldsm4(uint32_t& r0, uint32_t& r1, uint32_t& r2, uint32_t& r3,
                                      uint32_t addr) {
    asm volatile("ldmatrix.sync.aligned.m8n8.x4.shared.b16 {%0,%1,%2,%3}, [%4];"
                 : "=r"(r0), "=r"(r1), "=r"(r2), "=r"(r3) : "r"(addr));
}

#define MMA_BF16(acc, a, b)                                                          \
    asm volatile(                                                                    \
        "mma.sync.aligned.m16n8k16.row.col.f32.bf16.bf16.f32 "                       \
        "{%0,%1,%2,%3},{%4,%5,%6,%7},{%8,%9},{%0,%1,%2,%3};"                         \
        : "+f"(acc[0]), "+f"(acc[1]), "+f"(acc[2]), "+f"(acc[3])                     \
        : "r"(a[0]), "r"(a[1]), "r"(a[2]), "r"(a[3]), "r"(b[0]), "r"(b[1]))

__device__ __forceinline__ float sigm(float x)   { return 1.f / (1.f + __expf(-x)); }
__device__ __forceinline__ float tanhff(float x) { return 1.f - 2.f / (__expf(2.f * x) + 1.f); }

// ---------------- prep (3 kernels so k_steps is the 4th launch for ncu) ----------------
__global__ void k_prep_x(const float* __restrict__ x) {
    // g_xt[t][b][k] = bf16(x[b][t][k]); i enumerates output-linear (t,b,k)
    const size_t stride = (size_t)gridDim.x * blockDim.x;
    for (size_t i = (size_t)blockIdx.x * blockDim.x + threadIdx.x;
         i < (size_t)SEQT * BATCH * INP; i += stride) {
        int k = (int)(i % INP);
        size_t tb = i / INP;
        int b = (int)(tb % BATCH);
        int t = (int)(tb / BATCH);
        g_xt[i] = __float2bfloat16_rn(x[((size_t)b * SEQT + t) * INP + k]);
    }
}

__global__ void k_prep_w(const float* __restrict__ wii, const float* __restrict__ wif,
                         const float* __restrict__ wic, const float* __restrict__ wio,
                         const float* __restrict__ whi, const float* __restrict__ whf,
                         const float* __restrict__ whc, const float* __restrict__ who) {
    const size_t stride = (size_t)gridDim.x * blockDim.x;
    const size_t t0 = (size_t)blockIdx.x * blockDim.x + threadIdx.x;
    for (size_t i = t0; i < (size_t)NG * INP; i += stride) {
        int n = (int)(i / INP), k = (int)(i % INP);
        int g = n & 3, j = n >> 2;
        const float* w = (g == 0) ? wii : (g == 1) ? wif : (g == 2) ? wic : wio;
        g_wi[i] = __float2bfloat16_rn(w[(size_t)j * INP + k]);
    }
    for (size_t i = t0; i < (size_t)NG * HID; i += stride) {
        int n = (int)(i / HID), k = (int)(i % HID);
        int g = n & 3, j = n >> 2;
        const float* w = (g == 0) ? whi : (g == 1) ? whf : (g == 2) ? whc : who;
        g_wh[i] = __float2bfloat16_rn(w[(size_t)j * HID + k]);
    }
}

__global__ void k_prep_b(const float* bii, const float* bhi, const float* bif, const float* bhf,
                         const float* bic, const float* bhc, const float* bio, const float* bho) {
    int i = blockIdx.x * blockDim.x + threadIdx.x;
    if (i < BATCH * HID) g_h[0][i] = __float2bfloat16_rn(0.f);
    if (i < NG) {
        int g = i & 3, j = i >> 2;
        float v;
        if (g == 0)      v = bii[j] + bhi[j];
        else if (g == 1) v = bif[j] + bhf[j];
        else if (g == 2) v = bic[j] + bhc[j];
        else             v = bio[j] + bho[j];
        g_bias[i] = v;
    }
    if (i < 2) g_barg[i] = 0u;
}

// ============================================================================
// Persistent fused step kernel: all 128 timesteps, input projection fused.
// Grid (64 n, 2 m) = 128 CTAs, 256 threads (8 warps 4m x 2n, warp tile 32x32).
// Persistent smem: Wh slice 64x1024 (128KB) + Wi slice 64x512 (64KB) + bias.
// Per step K-loop: 16 x-slabs (B from Wi) then 32 h-slabs (B from Wh),
// BK=32, 3-stage A ring, 1 barrier/slab. Epilogue: pre-tile (aliases A ring)
// + bias, fused LSTM, c in registers. Per-m-group grid barrier (the two
// batch halves are independent chains).
// Smem: [0,128K) Wh | [128K,192K) Wi | [192K, +33280) A-ring(24K)/pre union |
//       [+33280, +256) bias.  Total 230144 B.
// ============================================================================
static const int WI_OFF   = 131072;
static const int U_OFF    = 196608;                // A-ring (3x8192) & pre-tile union
static const int BIAS_OFF = U_OFF + 33280;         // 229888
static const int S_SMEM   = BIAS_OFF + 256;        // 230144

__global__ __launch_bounds__(256, 1) void k_steps() {
    extern __shared__ char smem[];
    const uint32_t sb = smem_u32(smem);
    const int tid = threadIdx.x, lane = tid & 31, wid = tid >> 5;
    const int wm = wid & 3, wn = wid >> 2;
    const int n0 = blockIdx.x * 64, m0 = blockIdx.y * 128;
    const int grp = blockIdx.y;

    // ---- persistent loads: Wh slice (128KB), Wi slice (64KB), bias (256B) ----
#pragma unroll
    for (int i = 0; i < 32; i++) {
        int idx = tid + i * 256;            // 8192 16B-chunks
        int row = idx >> 7, c = idx & 127;
        cp16s(sb + whsw(row, c), g_wh + (size_t)(n0 + row) * HID + c * 8);
    }
#pragma unroll
    for (int i = 0; i < 16; i++) {
        int idx = tid + i * 256;            // 4096 16B-chunks
        int row = idx >> 6, c = idx & 63;
        cp16s(sb + WI_OFF + wisw(row, c), g_wi + (size_t)(n0 + row) * INP + c * 8);
    }
    if (tid < 16)
        cp16s(sb + BIAS_OFF + tid * 16, &g_bias[n0 + tid * 4]);
    CP_COMMIT();

    float creg[8];
#pragma unroll
    for (int q = 0; q < 8; q++) creg[q] = 0.f;

    float* pre = (float*)(smem + U_OFF);
    const float* bias4 = (const float*)(smem + BIAS_OFF);
    const int NS = 48;   // 16 x-slabs + 32 h-slabs

    for (int t = 0; t < SEQT; t++) {
        const __nv_bfloat16* __restrict__ hin = g_h[t & 1];
        __nv_bfloat16* __restrict__ hout = g_h[(t + 1) & 1];
        const __nv_bfloat16* __restrict__ xt = g_xt + (size_t)t * BATCH * INP;

        float acc[2][4][4];
#pragma unroll
        for (int mi = 0; mi < 2; mi++)
#pragma unroll
            for (int ni = 0; ni < 4; ni++)
#pragma unroll
                for (int q = 0; q < 4; q++) acc[mi][ni][q] = 0.f;

        auto load_slab = [&](int s) {
            const uint32_t ab = sb + U_OFF + (uint32_t)(s % 3) * 8192u;
            const __nv_bfloat16* src;
            int k0;
            if (s < 16) { src = xt;  k0 = s * 32; }          // x slab, K=512
            else        { src = hin; k0 = (s - 16) * 32; }   // h slab, K=1024
            const int kstride = (s < 16) ? INP : HID;
#pragma unroll
            for (int i = 0; i < 2; i++) {   // A: 128 rows x 4 chunks
                int q = tid + i * 256, row = q >> 2, c = q & 3;
                cp16s(ab + sw(row, c), src + (size_t)(m0 + row) * kstride + k0 + c * 8);
            }
        };

        load_slab(0); CP_COMMIT();
        load_slab(1); CP_COMMIT();
#pragma unroll 1
        for (int s = 0; s < NS; s++) {
            if (s + 1 < NS) CP_WAIT1(); else CP_WAIT0();
            __syncthreads();
            if (s + 2 < NS) { load_slab(s + 2); CP_COMMIT(); }
            const uint32_t ab = sb + U_OFF + (uint32_t)(s % 3) * 8192u;
#pragma unroll
            for (int ks = 0; ks < 2; ks++) {
                uint32_t a[2][4];
#pragma unroll
                for (int mi = 0; mi < 2; mi++) {
                    int row = wm * 32 + mi * 16 + (lane & 15);
                    int c = 2 * ks + (lane >> 4);
                    ldsm4(a[mi][0], a[mi][1], a[mi][2], a[mi][3], ab + sw(row, c));
                }
                uint32_t b[4][2];
#pragma unroll
                for (int nt = 0; nt < 2; nt++) {
                    int row = wn * 32 + nt * 16 + ((lane >> 4) << 3) + (lane & 7);
                    int c2 = 2 * ks + ((lane >> 3) & 1);
                    uint32_t baddr;
                    if (s < 16) baddr = sb + WI_OFF + wisw(row, s * 4 + c2);
                    else        baddr = sb + whsw(row, (s - 16) * 4 + c2);
                    ldsm4(b[2 * nt][0], b[2 * nt][1], b[2 * nt + 1][0], b[2 * nt + 1][1],
                          baddr);
                }
#pragma unroll
                for (int mi = 0; mi < 2; mi++)
#pragma unroll
                    for (int ni = 0; ni < 4; ni++) MMA_BF16(acc[mi][ni], a[mi], b[ni]);
            }
        }
        __syncthreads();   // A-ring free; pre-tile aliases it

        // scatter acc -> pre-tile [128][64], stride 65
        const int lr = lane >> 2, lc = lane & 3;
#pragma unroll
        for (int mi = 0; mi < 2; mi++)
#pragma unroll
            for (int ni = 0; ni < 4; ni++) {
                int r = wm * 32 + mi * 16 + lr;
                int cc = wn * 32 + ni * 8 + 2 * lc;
                pre[r * 65 + cc]           = acc[mi][ni][0];
                pre[r * 65 + cc + 1]       = acc[mi][ni][1];
                pre[(r + 8) * 65 + cc]     = acc[mi][ni][2];
                pre[(r + 8) * 65 + cc + 1] = acc[mi][ni][3];
            }
        __syncthreads();

        // fused LSTM elementwise: 8 (b,j) pairs per thread
#pragma unroll
        for (int s = 0; s < 8; s++) {
            int p = s * 256 + tid;
            int r = p >> 4, jj = p & 15;
            int b = m0 + r;
            float4 b4 = *(const float4*)&bias4[4 * jj];
            float p0 = pre[r * 65 + 4 * jj + 0] + b4.x;
            float p1 = pre[r * 65 + 4 * jj + 1] + b4.y;
            float p2 = pre[r * 65 + 4 * jj + 2] + b4.z;
            float p3 = pre[r * 65 + 4 * jj + 3] + b4.w;
            float ig = sigm(p0);
            float fg = sigm(p1);
            float gg = tanhff(p2);
            float og = sigm(p3);
            float cn = fg * creg[s] + ig * gg;
            creg[s] = cn;
            hout[b * HID + (n0 >> 2) + jj] = __float2bfloat16_rn(og * tanhff(cn));
        }

        // ---- per-m-group grid barrier (64 CTAs; the two groups are independent) ----
        __threadfence();
        __syncthreads();
        if (tid == 0) {
            atomicAdd(&g_barg[grp], 1u);
            unsigned target = (unsigned)(t + 1) * 64u;
            while (*(volatile unsigned*)&g_barg[grp] < target) { }
        }
        __syncthreads();
        __threadfence();
    }
}

// ---------------- final FC + log_softmax ----------------
__global__ void k_final(const float* __restrict__ wfc, float* __restrict__ out) {
    __shared__ float hs[HID];
    __shared__ float logits[NOUT];
    const int b = blockIdx.x, tid = threadIdx.x;
    const __nv_bfloat16* h = g_h[0];   // t=127 wrote buffer (128 & 1) == 0
    for (int i = tid; i < HID; i += 256) hs[i] = __bfloat162float(h[b * HID + i]);
    __syncthreads();

    const int warp = tid >> 5, lane = tid & 31;
#pragma unroll
    for (int oo = 0; oo < 4; oo++) {
        int o = warp * 4 + oo;
        float s = 0.f;
        for (int k = lane; k < HID; k += 32) s += hs[k] * wfc[o * HID + k];
#pragma unroll
        for (int off = 16; off; off >>= 1) s += __shfl_xor_sync(0xffffffffu, s, off);
        if (lane == 0) logits[o] = s;
    }
    __syncthreads();

    if (tid < 32) {
        float l = logits[tid];
        float m = l;
#pragma unroll
        for (int off = 16; off; off >>= 1) m = fmaxf(m, __shfl_xor_sync(0xffffffffu, m, off));
        float e = expf(l - m);
        float se = e;
#pragma unroll
        for (int off = 16; off; off >>= 1) se += __shfl_xor_sync(0xffffffffu, se, off);
        out[b * NOUT + tid] = l - m - logf(se);
    }
}

// ---------------- launch ----------------
extern "C" void kernel_launch(void* const* d_in, const int* in_sizes, int n_in,
                              void* d_out, int out_size) {
    const float* x    = (const float*)d_in[0];
    const float* w_ii = (const float*)d_in[1];
    const float* w_hi = (const float*)d_in[2];
    const float* b_ii = (const float*)d_in[3];
    const float* b_hi = (const float*)d_in[4];
    const float* w_if = (const float*)d_in[5];
    const float* w_hf = (const float*)d_in[6];
    const float* b_if = (const float*)d_in[7];
    const float* b_hf = (const float*)d_in[8];
    const float* w_io = (const float*)d_in[9];
    const float* w_ho = (const float*)d_in[10];
    const float* b_io = (const float*)d_in[11];
    const float* b_ho = (const float*)d_in[12];
    const float* w_ic = (const float*)d_in[13];
    const float* w_hc = (const float*)d_in[14];
    const float* b_ic = (const float*)d_in[15];
    const float* b_hc = (const float*)d_in[16];
    const float* w_fc = (const float*)d_in[17];

    cudaFuncSetAttribute(k_steps, cudaFuncAttributeMaxDynamicSharedMemorySize, S_SMEM);

    k_prep_x<<<2048, 256>>>(x);
    k_prep_w<<<2048, 256>>>(w_ii, w_if, w_ic, w_io, w_hi, w_hf, w_hc, w_ho);
    k_prep_b<<<1024, 256>>>(b_ii, b_hi, b_if, b_hf, b_ic, b_hc, b_io, b_ho);

    k_steps<<<dim3(64, 2), 256, S_SMEM>>>();

    k_final<<<BATCH, 256>>>(w_fc, (float*)d_out);
}

// round 9
// speedup vs baseline: 1.1211x; 1.1211x over previous
#include <cuda_runtime.h>
#include <cuda_bf16.h>
#include <cstdint>
#include <math.h>

#define BATCH 256
#define SEQT  128
#define INP   512
#define HID   1024
#define NOUT  32
#define NG    4096   // 4*HID, interleaved gates: n = 4*j + g (0=i,1=f,2=cell,3=o)

// ---------------- scratch (device globals; no cudaMalloc allowed) ----------------
__device__ float         g_gx[(size_t)BATCH * SEQT * NG];    // input-proj preacts + bias (fp32)
__device__ __nv_bfloat16 g_xr[(size_t)BATCH * SEQT * INP];   // bf16 inputs
__device__ __nv_bfloat16 g_wi[(size_t)NG * INP];             // packed bf16 input weights
__device__ __nv_bfloat16 g_wh[(size_t)NG * HID];             // packed bf16 hidden weights
__device__ float         g_bias[NG];
__device__ __nv_bfloat16 g_h[2][BATCH * HID];                // double-buffered hidden state
__device__ unsigned      g_barg[2];                          // per-m-group barrier counters

// ---------------- helpers ----------------
__device__ __forceinline__ uint32_t smem_u32(const void* p) {
    return (uint32_t)__cvta_generic_to_shared(p);
}
__device__ __forceinline__ void cp16s(uint32_t dst, const void* src) {
    asm volatile("cp.async.cg.shared.global [%0], [%1], 16;" :: "r"(dst), "l"(src));
}
#define CP_COMMIT() asm volatile("cp.async.commit_group;" ::: "memory")
#define CP_WAIT0()  asm volatile("cp.async.wait_group 0;" ::: "memory")
#define CP_WAIT2()  asm volatile("cp.async.wait_group 2;" ::: "memory")

// 64B-row smem layout (BK=32 bf16), 16B chunk swizzle (R4-proven).
__device__ __forceinline__ uint32_t sw(int row, int c) {
    return (uint32_t)(row * 64 + ((c ^ ((row >> 1) & 3)) << 4));
}
// Persistent Wh smem: 2KB rows (K=1024 bf16), per-row chunk swizzle.
__device__ __forceinline__ uint32_t whsw(int row, int c) {
    return (uint32_t)(row * 2048 + ((c ^ (row & 7)) << 4));
}

__device__ __forceinline__ void ldsm4(uint32_t& r0, uint32_t& r1, uint32_t& r2, uint32_t& r3,
                                      uint32_t addr) {
    asm volatile("ldmatrix.sync.aligned.m8n8.x4.shared.b16 {%0,%1,%2,%3}, [%4];"
                 : "=r"(r0), "=r"(r1), "=r"(r2), "=r"(r3) : "r"(addr));
}

#define MMA_BF16(acc, a, b)                                                          \
    asm volatile(                                                                    \
        "mma.sync.aligned.m16n8k16.row.col.f32.bf16.bf16.f32 "                       \
        "{%0,%1,%2,%3},{%4,%5,%6,%7},{%8,%9},{%0,%1,%2,%3};"                         \
        : "+f"(acc[0]), "+f"(acc[1]), "+f"(acc[2]), "+f"(acc[3])                     \
        : "r"(a[0]), "r"(a[1]), "r"(a[2]), "r"(a[3]), "r"(b[0]), "r"(b[1]))

__device__ __forceinline__ float sigm(float x)   { return 1.f / (1.f + __expf(-x)); }
__device__ __forceinline__ float tanhff(float x) { return 1.f - 2.f / (__expf(2.f * x) + 1.f); }

// ---------------- prep (2 kernels so k_steps is the 4th launch for ncu) ----------------
__global__ void k_prep0(const float* __restrict__ x,
                        const float* __restrict__ wii, const float* __restrict__ wif,
                        const float* __restrict__ wic, const float* __restrict__ wio,
                        const float* __restrict__ whi, const float* __restrict__ whf,
                        const float* __restrict__ whc, const float* __restrict__ who) {
    const size_t stride = (size_t)gridDim.x * blockDim.x;
    const size_t t0 = (size_t)blockIdx.x * blockDim.x + threadIdx.x;
    for (size_t i = t0; i < (size_t)BATCH * SEQT * INP; i += stride)
        g_xr[i] = __float2bfloat16_rn(x[i]);
    for (size_t i = t0; i < (size_t)NG * INP; i += stride) {
        int n = (int)(i / INP), k = (int)(i % INP);
        int g = n & 3, j = n >> 2;
        const float* w = (g == 0) ? wii : (g == 1) ? wif : (g == 2) ? wic : wio;
        g_wi[i] = __float2bfloat16_rn(w[(size_t)j * INP + k]);
    }
    for (size_t i = t0; i < (size_t)NG * HID; i += stride) {
        int n = (int)(i / HID), k = (int)(i % HID);
        int g = n & 3, j = n >> 2;
        const float* w = (g == 0) ? whi : (g == 1) ? whf : (g == 2) ? whc : who;
        g_wh[i] = __float2bfloat16_rn(w[(size_t)j * HID + k]);
    }
}

__global__ void k_prep1(const float* bii, const float* bhi, const float* bif, const float* bhf,
                        const float* bic, const float* bhc, const float* bio, const float* bho) {
    int i = blockIdx.x * blockDim.x + threadIdx.x;
    if (i < BATCH * HID) g_h[0][i] = __float2bfloat16_rn(0.f);
    if (i < NG) {
        int g = i & 3, j = i >> 2;
        float v;
        if (g == 0)      v = bii[j] + bhi[j];
        else if (g == 1) v = bif[j] + bhf[j];
        else if (g == 2) v = bic[j] + bhc[j];
        else             v = bio[j] + bho[j];
        g_bias[i] = v;
    }
    if (i < 2) g_barg[i] = 0u;
}

// ============================================================================
// Input GEMM: g_gx = Xr @ Wi^T + bias.  CTA tile 128 x 128, K=512, BK=32,
// 8-stage cp.async ring, TWO slabs per wait/sync (9 syncs total).
// 8 warps as 4m x 2n; warp tile 32x64. Grid (32 n, 256 m). 128KB smem.
// ============================================================================
static const int X_SMEM = 131072;

__global__ __launch_bounds__(256, 1) void k_gemm_x() {
    extern __shared__ char smem[];
    const uint32_t sb = smem_u32(smem);
    const int tid = threadIdx.x, lane = tid & 31, wid = tid >> 5;
    const int wm = wid & 3, wn = wid >> 2;
    const int n0 = blockIdx.x * 128, m0 = blockIdx.y * 128;

    float acc[2][8][4];
#pragma unroll
    for (int mi = 0; mi < 2; mi++)
#pragma unroll
        for (int ni = 0; ni < 8; ni++)
#pragma unroll
            for (int q = 0; q < 4; q++) acc[mi][ni][q] = 0.f;

    auto load_slab = [&](int s) {
        const uint32_t ab = sb + (uint32_t)(s & 7) * 16384u;
        const int k0 = s * 32;
#pragma unroll
        for (int i = 0; i < 2; i++) {
            int q = tid + i * 256, row = q >> 2, c = q & 3;
            cp16s(ab + sw(row, c), g_xr + (size_t)(m0 + row) * INP + k0 + c * 8);
        }
#pragma unroll
        for (int i = 0; i < 2; i++) {
            int q = tid + i * 256, row = q >> 2, c = q & 3;
            cp16s(ab + 8192u + sw(row, c), g_wi + (size_t)(n0 + row) * INP + k0 + c * 8);
        }
    };

    auto do_slab = [&](int s) {
        const uint32_t ab = sb + (uint32_t)(s & 7) * 16384u;
        const uint32_t bb = ab + 8192u;
#pragma unroll
        for (int ks = 0; ks < 2; ks++) {
            uint32_t a[2][4];
#pragma unroll
            for (int mi = 0; mi < 2; mi++) {
                int row = wm * 32 + mi * 16 + (lane & 15);
                int c = 2 * ks + (lane >> 4);
                ldsm4(a[mi][0], a[mi][1], a[mi][2], a[mi][3], ab + sw(row, c));
            }
            uint32_t b[8][2];
#pragma unroll
            for (int nt = 0; nt < 4; nt++) {
                int row = wn * 64 + nt * 16 + ((lane >> 4) << 3) + (lane & 7);
                int c = 2 * ks + ((lane >> 3) & 1);
                ldsm4(b[2 * nt][0], b[2 * nt][1], b[2 * nt + 1][0], b[2 * nt + 1][1],
                      bb + sw(row, c));
            }
#pragma unroll
            for (int mi = 0; mi < 2; mi++)
#pragma unroll
                for (int ni = 0; ni < 8; ni++) MMA_BF16(acc[mi][ni], a[mi], b[ni]);
        }
    };

    // 16 slabs, 8 iterations of 2
    load_slab(0); CP_COMMIT();
    load_slab(1); CP_COMMIT();
    load_slab(2); CP_COMMIT();
    load_slab(3); CP_COMMIT();
    for (int j = 0; j < 8; j++) {
        if (j < 7) CP_WAIT2(); else CP_WAIT0();
        __syncthreads();
        if (2 * j + 4 < 16) { load_slab(2 * j + 4); CP_COMMIT(); }
        if (2 * j + 5 < 16) { load_slab(2 * j + 5); CP_COMMIT(); }
        do_slab(2 * j);
        do_slab(2 * j + 1);
    }

    const int lr = lane >> 2, lc = lane & 3;
#pragma unroll
    for (int mi = 0; mi < 2; mi++)
#pragma unroll
        for (int ni = 0; ni < 8; ni++) {
            int r = wm * 32 + mi * 16 + lr;
            int cc = wn * 64 + ni * 8 + 2 * lc;
            int n = n0 + cc;
            float b0 = g_bias[n], b1 = g_bias[n + 1];
            float2 v0 = { acc[mi][ni][0] + b0, acc[mi][ni][1] + b1 };
            float2 v1 = { acc[mi][ni][2] + b0, acc[mi][ni][3] + b1 };
            *reinterpret_cast<float2*>(&g_gx[(size_t)(m0 + r) * NG + n])     = v0;
            *reinterpret_cast<float2*>(&g_gx[(size_t)(m0 + r + 8) * NG + n]) = v1;
        }
}

// ============================================================================
// Persistent step kernel (R7 mainloop math): 256 threads, 8 warps 4m x 2n,
// warp tile 32x32, BK=32.  NEW: 8-stage A ring with TWO slabs per wait/sync
// (17 syncs/step vs 32), per-m-group grid barrier.  gx epilogue tile
// prefetched to smem; fast tanh; c-state in registers.
// Smem: [0,128K) Wh | [128K,+64K) A-ring (pre-tile aliases first 33280B) |
//       [192K,+32K) gx | [+,256) bias.  Total 229632 B.
// ============================================================================
static const int RING_OFF = 131072;
static const int PRE_OFF  = 131072;                // aliases ring (post-mainloop only)
static const int GX_OFF   = 131072 + 65536;        // 196608
static const int BIAS_OFF = GX_OFF + 32768;        // 229376
static const int S_SMEM   = BIAS_OFF + 256;        // 229632

__global__ __launch_bounds__(256, 1) void k_steps() {
    extern __shared__ char smem[];
    const uint32_t sb = smem_u32(smem);
    const int tid = threadIdx.x, lane = tid & 31, wid = tid >> 5;
    const int wm = wid & 3, wn = wid >> 2;
    const int n0 = blockIdx.x * 64, m0 = blockIdx.y * 128;
    const int grp = blockIdx.y;

    // ---- persistent loads: Wh slice (128KB) + bias (256B) ----
#pragma unroll
    for (int i = 0; i < 32; i++) {
        int idx = tid + i * 256;            // 8192 16B-chunks
        int row = idx >> 7, c = idx & 127;
        cp16s(sb + whsw(row, c), g_wh + (size_t)(n0 + row) * HID + c * 8);
    }
    if (tid < 16)
        cp16s(sb + BIAS_OFF + tid * 16, &g_bias[n0 + tid * 4]);
    CP_COMMIT();

    float creg[8];
#pragma unroll
    for (int q = 0; q < 8; q++) creg[q] = 0.f;

    float* pre = (float*)(smem + PRE_OFF);
    const float* gxs = (const float*)(smem + GX_OFF);
    const float* bias4 = (const float*)(smem + BIAS_OFF);

    for (int t = 0; t < SEQT; t++) {
        const __nv_bfloat16* __restrict__ hin = g_h[t & 1];
        __nv_bfloat16* __restrict__ hout = g_h[(t + 1) & 1];

        float acc[2][4][4];
#pragma unroll
        for (int mi = 0; mi < 2; mi++)
#pragma unroll
            for (int ni = 0; ni < 4; ni++)
#pragma unroll
                for (int q = 0; q < 4; q++) acc[mi][ni][q] = 0.f;

        auto load_slab = [&](int s) {
            const uint32_t ab = sb + RING_OFF + (uint32_t)(s & 7) * 8192u;
            const int k0 = s * 32;
#pragma unroll
            for (int i = 0; i < 2; i++) {   // A: 128 rows x 4 chunks
                int q = tid + i * 256, row = q >> 2, c = q & 3;
                cp16s(ab + sw(row, c), hin + (size_t)(m0 + row) * HID + k0 + c * 8);
            }
        };

        auto do_slab = [&](int s) {
            const uint32_t ab = sb + RING_OFF + (uint32_t)(s & 7) * 8192u;
#pragma unroll
            for (int ks = 0; ks < 2; ks++) {
                uint32_t a[2][4];
#pragma unroll
                for (int mi = 0; mi < 2; mi++) {
                    int row = wm * 32 + mi * 16 + (lane & 15);
                    int c = 2 * ks + (lane >> 4);
                    ldsm4(a[mi][0], a[mi][1], a[mi][2], a[mi][3], ab + sw(row, c));
                }
                uint32_t b[4][2];
#pragma unroll
                for (int nt = 0; nt < 2; nt++) {
                    int row = wn * 32 + nt * 16 + ((lane >> 4) << 3) + (lane & 7);
                    int gc = s * 4 + 2 * ks + ((lane >> 3) & 1);
                    ldsm4(b[2 * nt][0], b[2 * nt][1], b[2 * nt + 1][0], b[2 * nt + 1][1],
                          sb + whsw(row, gc));
                }
#pragma unroll
                for (int mi = 0; mi < 2; mi++)
#pragma unroll
                    for (int ni = 0; ni < 4; ni++) MMA_BF16(acc[mi][ni], a[mi], b[ni]);
            }
        };

        // prologue: slabs 0-3; gx epilogue tile rides with slab 3's group
        load_slab(0); CP_COMMIT();
        load_slab(1); CP_COMMIT();
        load_slab(2); CP_COMMIT();
        load_slab(3);
#pragma unroll
        for (int i = 0; i < 8; i++) {       // gx: 2048 16B-chunks, 8/thread
            int idx = tid + i * 256;
            int row = idx >> 4, c = idx & 15;
            cp16s(sb + GX_OFF + (uint32_t)(row * 256 + c * 16),
                  &g_gx[((size_t)(m0 + row) * SEQT + t) * NG + n0 + c * 4]);
        }
        CP_COMMIT();

        // 32 slabs, 16 iterations of 2
        for (int j = 0; j < 16; j++) {
            if (j < 15) CP_WAIT2(); else CP_WAIT0();
            __syncthreads();
            if (2 * j + 4 < 32) { load_slab(2 * j + 4); CP_COMMIT(); }
            if (2 * j + 5 < 32) { load_slab(2 * j + 5); CP_COMMIT(); }
            do_slab(2 * j);
            do_slab(2 * j + 1);
        }
        __syncthreads();   // ring free; pre-tile aliases it

        // scatter acc -> pre-tile [128][64], stride 65
        const int lr = lane >> 2, lc = lane & 3;
#pragma unroll
        for (int mi = 0; mi < 2; mi++)
#pragma unroll
            for (int ni = 0; ni < 4; ni++) {
                int r = wm * 32 + mi * 16 + lr;
                int cc = wn * 32 + ni * 8 + 2 * lc;
                pre[r * 65 + cc]           = acc[mi][ni][0];
                pre[r * 65 + cc + 1]       = acc[mi][ni][1];
                pre[(r + 8) * 65 + cc]     = acc[mi][ni][2];
                pre[(r + 8) * 65 + cc + 1] = acc[mi][ni][3];
            }
        __syncthreads();

        // fused LSTM elementwise: 8 (b,j) pairs per thread (gx from smem)
#pragma unroll
        for (int s = 0; s < 8; s++) {
            int p = s * 256 + tid;
            int r = p >> 4, jj = p & 15;
            int b = m0 + r;
            float4 gx4 = *(const float4*)&gxs[r * 64 + 4 * jj];
            float p0 = pre[r * 65 + 4 * jj + 0] + gx4.x;
            float p1 = pre[r * 65 + 4 * jj + 1] + gx4.y;
            float p2 = pre[r * 65 + 4 * jj + 2] + gx4.z;
            float p3 = pre[r * 65 + 4 * jj + 3] + gx4.w;
            float ig = sigm(p0);
            float fg = sigm(p1);
            float gg = tanhff(p2);
            float og = sigm(p3);
            float cn = fg * creg[s] + ig * gg;
            creg[s] = cn;
            hout[b * HID + (n0 >> 2) + jj] = __float2bfloat16_rn(og * tanhff(cn));
        }

        // ---- per-m-group grid barrier (64 CTAs; groups independent) ----
        __threadfence();
        __syncthreads();
        if (tid == 0) {
            atomicAdd(&g_barg[grp], 1u);
            unsigned target = (unsigned)(t + 1) * 64u;
            while (*(volatile unsigned*)&g_barg[grp] < target) { }
        }
        __syncthreads();
        __threadfence();
    }
}

// ---------------- final FC + log_softmax ----------------
__global__ void k_final(const float* __restrict__ wfc, float* __restrict__ out) {
    __shared__ float hs[HID];
    __shared__ float logits[NOUT];
    const int b = blockIdx.x, tid = threadIdx.x;
    const __nv_bfloat16* h = g_h[0];   // t=127 wrote buffer (128 & 1) == 0
    for (int i = tid; i < HID; i += 256) hs[i] = __bfloat162float(h[b * HID + i]);
    __syncthreads();

    const int warp = tid >> 5, lane = tid & 31;
#pragma unroll
    for (int oo = 0; oo < 4; oo++) {
        int o = warp * 4 + oo;
        float s = 0.f;
        for (int k = lane; k < HID; k += 32) s += hs[k] * wfc[o * HID + k];
#pragma unroll
        for (int off = 16; off; off >>= 1) s += __shfl_xor_sync(0xffffffffu, s, off);
        if (lane == 0) logits[o] = s;
    }
    __syncthreads();

    if (tid < 32) {
        float l = logits[tid];
        float m = l;
#pragma unroll
        for (int off = 16; off; off >>= 1) m = fmaxf(m, __shfl_xor_sync(0xffffffffu, m, off));
        float e = expf(l - m);
        float se = e;
#pragma unroll
        for (int off = 16; off; off >>= 1) se += __shfl_xor_sync(0xffffffffu, se, off);
        out[b * NOUT + tid] = l - m - logf(se);
    }
}

// ---------------- launch ----------------
extern "C" void kernel_launch(void* const* d_in, const int* in_sizes, int n_in,
                              void* d_out, int out_size) {
    const float* x    = (const float*)d_in[0];
    const float* w_ii = (const float*)d_in[1];
    const float* w_hi = (const float*)d_in[2];
    const float* b_ii = (const float*)d_in[3];
    const float* b_hi = (const float*)d_in[4];
    const float* w_if = (const float*)d_in[5];
    const float* w_hf = (const float*)d_in[6];
    const float* b_if = (const float*)d_in[7];
    const float* b_hf = (const float*)d_in[8];
    const float* w_io = (const float*)d_in[9];
    const float* w_ho = (const float*)d_in[10];
    const float* b_io = (const float*)d_in[11];
    const float* b_ho = (const float*)d_in[12];
    const float* w_ic = (const float*)d_in[13];
    const float* w_hc = (const float*)d_in[14];
    const float* b_ic = (const float*)d_in[15];
    const float* b_hc = (const float*)d_in[16];
    const float* w_fc = (const float*)d_in[17];

    cudaFuncSetAttribute(k_gemm_x, cudaFuncAttributeMaxDynamicSharedMemorySize, X_SMEM);
    cudaFuncSetAttribute(k_steps,  cudaFuncAttributeMaxDynamicSharedMemorySize, S_SMEM);

    k_prep0<<<2048, 256>>>(x, w_ii, w_if, w_ic, w_io, w_hi, w_hf, w_hc, w_ho);
    k_prep1<<<1024, 256>>>(b_ii, b_hi, b_if, b_hf, b_ic, b_hc, b_io, b_ho);

    k_gemm_x<<<dim3(32, 256), 256, X_SMEM>>>();

    k_steps<<<dim3(64, 2), 256, S_SMEM>>>();

    k_final<<<BATCH, 256>>>(w_fc, (float*)d_out);
}

// round 10
// speedup vs baseline: 1.2776x; 1.1396x over previous
#include <cuda_runtime.h>
#include <cuda_bf16.h>
#include <cstdint>
#include <math.h>

#define BATCH 256
#define SEQT  128
#define INP   512
#define HID   1024
#define NOUT  32
#define NG    4096   // 4*HID, interleaved gates: n = 4*j + g (0=i,1=f,2=cell,3=o)

// ---------------- scratch (device globals; no cudaMalloc allowed) ----------------
__device__ float         g_gx[(size_t)BATCH * SEQT * NG];    // input-proj preacts + bias (fp32)
__device__ __nv_bfloat16 g_xr[(size_t)BATCH * SEQT * INP];   // bf16 inputs
__device__ __nv_bfloat16 g_wi[(size_t)NG * INP];             // packed bf16 input weights
__device__ __nv_bfloat16 g_wh[(size_t)NG * HID];             // packed bf16 hidden weights
__device__ float         g_bias[NG];
__device__ __nv_bfloat16 g_h[2][BATCH * HID];                // double-buffered hidden state
__device__ unsigned      g_barg[2];                          // per-m-group barrier counters

// ---------------- helpers ----------------
__device__ __forceinline__ uint32_t smem_u32(const void* p) {
    return (uint32_t)__cvta_generic_to_shared(p);
}
__device__ __forceinline__ void cp16s(uint32_t dst, const void* src) {
    asm volatile("cp.async.cg.shared.global [%0], [%1], 16;" :: "r"(dst), "l"(src));
}
#define CP_COMMIT() asm volatile("cp.async.commit_group;" ::: "memory")
#define CP_WAIT0()  asm volatile("cp.async.wait_group 0;" ::: "memory")
#define CP_WAIT1()  asm volatile("cp.async.wait_group 1;" ::: "memory")

// 64B-row smem layout (BK=32 bf16), 16B chunk swizzle (R4-proven).
__device__ __forceinline__ uint32_t sw(int row, int c) {
    return (uint32_t)(row * 64 + ((c ^ ((row >> 1) & 3)) << 4));
}
// Persistent Wh smem: 2KB rows (K=1024 bf16), per-row chunk swizzle.
__device__ __forceinline__ uint32_t whsw(int row, int c) {
    return (uint32_t)(row * 2048 + ((c ^ (row & 7)) << 4));
}

__device__ __forceinline__ void ldsm4(uint32_t& r0, uint32_t& r1, uint32_t& r2, uint32_t& r3,
                                      uint32_t addr) {
    asm volatile("ldmatrix.sync.aligned.m8n8.x4.shared.b16 {%0,%1,%2,%3}, [%4];"
                 : "=r"(r0), "=r"(r1), "=r"(r2), "=r"(r3) : "r"(addr));
}

#define MMA_BF16(acc, a, b)                                                          \
    asm volatile(                                                                    \
        "mma.sync.aligned.m16n8k16.row.col.f32.bf16.bf16.f32 "                       \
        "{%0,%1,%2,%3},{%4,%5,%6,%7},{%8,%9},{%0,%1,%2,%3};"                         \
        : "+f"(acc[0]), "+f"(acc[1]), "+f"(acc[2]), "+f"(acc[3])                     \
        : "r"(a[0]), "r"(a[1]), "r"(a[2]), "r"(a[3]), "r"(b[0]), "r"(b[1]))

__device__ __forceinline__ float sigm(float x)   { return 1.f / (1.f + __expf(-x)); }
__device__ __forceinline__ float tanhff(float x) { return 1.f - 2.f / (__expf(2.f * x) + 1.f); }

// ---------------- prep (2 kernels so k_steps is the 4th launch for ncu) ----------------
__global__ void k_prep0(const float* __restrict__ x,
                        const float* __restrict__ wii, const float* __restrict__ wif,
                        const float* __restrict__ wic, const float* __restrict__ wio,
                        const float* __restrict__ whi, const float* __restrict__ whf,
                        const float* __restrict__ whc, const float* __restrict__ who) {
    const size_t stride = (size_t)gridDim.x * blockDim.x;
    const size_t t0 = (size_t)blockIdx.x * blockDim.x + threadIdx.x;
    for (size_t i = t0; i < (size_t)BATCH * SEQT * INP; i += stride)
        g_xr[i] = __float2bfloat16_rn(x[i]);
    for (size_t i = t0; i < (size_t)NG * INP; i += stride) {
        int n = (int)(i / INP), k = (int)(i % INP);
        int g = n & 3, j = n >> 2;
        const float* w = (g == 0) ? wii : (g == 1) ? wif : (g == 2) ? wic : wio;
        g_wi[i] = __float2bfloat16_rn(w[(size_t)j * INP + k]);
    }
    for (size_t i = t0; i < (size_t)NG * HID; i += stride) {
        int n = (int)(i / HID), k = (int)(i % HID);
        int g = n & 3, j = n >> 2;
        const float* w = (g == 0) ? whi : (g == 1) ? whf : (g == 2) ? whc : who;
        g_wh[i] = __float2bfloat16_rn(w[(size_t)j * HID + k]);
    }
}

__global__ void k_prep1(const float* bii, const float* bhi, const float* bif, const float* bhf,
                        const float* bic, const float* bhc, const float* bio, const float* bho) {
    int i = blockIdx.x * blockDim.x + threadIdx.x;
    if (i < BATCH * HID) g_h[0][i] = __float2bfloat16_rn(0.f);
    if (i < NG) {
        int g = i & 3, j = i >> 2;
        float v;
        if (g == 0)      v = bii[j] + bhi[j];
        else if (g == 1) v = bif[j] + bhf[j];
        else if (g == 2) v = bic[j] + bhc[j];
        else             v = bio[j] + bho[j];
        g_bias[i] = v;
    }
    if (i < 2) g_barg[i] = 0u;
}

// ============================================================================
// Input GEMM (R7/R4-proven, byte-identical): g_gx = Xr @ Wi^T + bias
// CTA tile 128 x 128, K=512, BK=32, 3-stage cp.async, 1 barrier/slab.
// 8 warps as 4m x 2n; warp tile 32x64. Grid (32 n, 256 m). 48KB smem.
// ============================================================================
static const int X_SMEM = 49152;

__global__ __launch_bounds__(256, 1) void k_gemm_x() {
    extern __shared__ char smem[];
    const uint32_t sb = smem_u32(smem);
    const int tid = threadIdx.x, lane = tid & 31, wid = tid >> 5;
    const int wm = wid & 3, wn = wid >> 2;
    const int n0 = blockIdx.x * 128, m0 = blockIdx.y * 128;

    float acc[2][8][4];
#pragma unroll
    for (int mi = 0; mi < 2; mi++)
#pragma unroll
        for (int ni = 0; ni < 8; ni++)
#pragma unroll
            for (int q = 0; q < 4; q++) acc[mi][ni][q] = 0.f;

    auto load_slab = [&](int s) {
        const uint32_t ab = sb + (uint32_t)(s % 3) * 16384u;
        const int k0 = s * 32;
#pragma unroll
        for (int i = 0; i < 2; i++) {
            int q = tid + i * 256, row = q >> 2, c = q & 3;
            cp16s(ab + sw(row, c), g_xr + (size_t)(m0 + row) * INP + k0 + c * 8);
        }
#pragma unroll
        for (int i = 0; i < 2; i++) {
            int q = tid + i * 256, row = q >> 2, c = q & 3;
            cp16s(ab + 8192u + sw(row, c), g_wi + (size_t)(n0 + row) * INP + k0 + c * 8);
        }
    };

    const int KT = INP / 32;
    load_slab(0); CP_COMMIT();
    load_slab(1); CP_COMMIT();
    for (int kt = 0; kt < KT; kt++) {
        if (kt + 1 < KT) CP_WAIT1(); else CP_WAIT0();
        __syncthreads();
        if (kt + 2 < KT) { load_slab(kt + 2); CP_COMMIT(); }
        const uint32_t ab = sb + (uint32_t)(kt % 3) * 16384u;
        const uint32_t bb = ab + 8192u;
#pragma unroll
        for (int ks = 0; ks < 2; ks++) {
            uint32_t a[2][4];
#pragma unroll
            for (int mi = 0; mi < 2; mi++) {
                int row = wm * 32 + mi * 16 + (lane & 15);
                int c = 2 * ks + (lane >> 4);
                ldsm4(a[mi][0], a[mi][1], a[mi][2], a[mi][3], ab + sw(row, c));
            }
            uint32_t b[8][2];
#pragma unroll
            for (int nt = 0; nt < 4; nt++) {
                int row = wn * 64 + nt * 16 + ((lane >> 4) << 3) + (lane & 7);
                int c = 2 * ks + ((lane >> 3) & 1);
                ldsm4(b[2 * nt][0], b[2 * nt][1], b[2 * nt + 1][0], b[2 * nt + 1][1],
                      bb + sw(row, c));
            }
#pragma unroll
            for (int mi = 0; mi < 2; mi++)
#pragma unroll
                for (int ni = 0; ni < 8; ni++) MMA_BF16(acc[mi][ni], a[mi], b[ni]);
        }
    }

    const int lr = lane >> 2, lc = lane & 3;
#pragma unroll
    for (int mi = 0; mi < 2; mi++)
#pragma unroll
        for (int ni = 0; ni < 8; ni++) {
            int r = wm * 32 + mi * 16 + lr;
            int cc = wn * 64 + ni * 8 + 2 * lc;
            int n = n0 + cc;
            float b0 = g_bias[n], b1 = g_bias[n + 1];
            float2 v0 = { acc[mi][ni][0] + b0, acc[mi][ni][1] + b1 };
            float2 v1 = { acc[mi][ni][2] + b0, acc[mi][ni][3] + b1 };
            *reinterpret_cast<float2*>(&g_gx[(size_t)(m0 + r) * NG + n])     = v0;
            *reinterpret_cast<float2*>(&g_gx[(size_t)(m0 + r + 8) * NG + n]) = v1;
        }
}

// ============================================================================
// Persistent step kernel: R7 mainloop byte-identical (256 thr, 8 warps 4m x 2n,
// warp tile 32x32, BK=32, 3-stage A ring, 1 barrier/slab, gx smem prefetch,
// fast tanh, c in registers).
// NEW vs R7 (outside the mainloop only):
//   (a) per-m-group grid barrier (2 independent chains, target 64/step),
//   (b) final FC + log_softmax fused after the t=127 barrier (k_final removed).
// Smem: [0,128K) Wh | [128K,+24K) A | [152K,+32K) gx | [184K,+32.5K) pre.
// ============================================================================
static const int A_OFF   = 131072;
static const int GX_OFF  = 131072 + 3 * 8192;            // 155648
static const int PRE_OFF = GX_OFF + 32768;               // 188416
static const int S_SMEM  = PRE_OFF + 33280;              // 221696

__global__ __launch_bounds__(256, 1) void k_steps(const float* __restrict__ wfc,
                                                  float* __restrict__ out) {
    extern __shared__ char smem[];
    const uint32_t sb = smem_u32(smem);
    const int tid = threadIdx.x, lane = tid & 31, wid = tid >> 5;
    const int wm = wid & 3, wn = wid >> 2;
    const int n0 = blockIdx.x * 64, m0 = blockIdx.y * 128;
    const int grp = blockIdx.y;

    // ---- load Wh slice (64 rows x 1024 bf16 = 128KB) into persistent smem ----
#pragma unroll
    for (int i = 0; i < 32; i++) {
        int idx = tid + i * 256;            // 8192 16B-chunks
        int row = idx >> 7, c = idx & 127;
        cp16s(sb + whsw(row, c), g_wh + (size_t)(n0 + row) * HID + c * 8);
    }
    CP_COMMIT();

    float creg[8];
#pragma unroll
    for (int q = 0; q < 8; q++) creg[q] = 0.f;

    float* pre = (float*)(smem + PRE_OFF);
    const float* gxs = (const float*)(smem + GX_OFF);
    const int KT = HID / 32;   // 32

    for (int t = 0; t < SEQT; t++) {
        const __nv_bfloat16* __restrict__ hin = g_h[t & 1];
        __nv_bfloat16* __restrict__ hout = g_h[(t + 1) & 1];

        float acc[2][4][4];
#pragma unroll
        for (int mi = 0; mi < 2; mi++)
#pragma unroll
            for (int ni = 0; ni < 4; ni++)
#pragma unroll
                for (int q = 0; q < 4; q++) acc[mi][ni][q] = 0.f;

        auto load_slab = [&](int s) {
            const uint32_t ab = sb + A_OFF + (uint32_t)(s % 3) * 8192u;
            const int k0 = s * 32;
#pragma unroll
            for (int i = 0; i < 2; i++) {   // A: 128 rows x 4 chunks
                int q = tid + i * 256, row = q >> 2, c = q & 3;
                cp16s(ab + sw(row, c), hin + (size_t)(m0 + row) * HID + k0 + c * 8);
            }
        };

        load_slab(0); CP_COMMIT();
        // slab 1 + gx epilogue tile (128 rows x 64 f32 = 32KB) in one group
        load_slab(1);
#pragma unroll
        for (int i = 0; i < 8; i++) {       // 2048 16B-chunks, 8/thread
            int idx = tid + i * 256;
            int row = idx >> 4, c = idx & 15;
            cp16s(sb + GX_OFF + (uint32_t)(row * 256 + c * 16),
                  &g_gx[((size_t)(m0 + row) * SEQT + t) * NG + n0 + c * 4]);
        }
        CP_COMMIT();

        for (int kt = 0; kt < KT; kt++) {
            if (kt + 1 < KT) CP_WAIT1(); else CP_WAIT0();
            __syncthreads();
            if (kt + 2 < KT) { load_slab(kt + 2); CP_COMMIT(); }
            const uint32_t ab = sb + A_OFF + (uint32_t)(kt % 3) * 8192u;
#pragma unroll
            for (int ks = 0; ks < 2; ks++) {
                uint32_t a[2][4];
#pragma unroll
                for (int mi = 0; mi < 2; mi++) {
                    int row = wm * 32 + mi * 16 + (lane & 15);
                    int c = 2 * ks + (lane >> 4);
                    ldsm4(a[mi][0], a[mi][1], a[mi][2], a[mi][3], ab + sw(row, c));
                }
                uint32_t b[4][2];
#pragma unroll
                for (int nt = 0; nt < 2; nt++) {
                    int row = wn * 32 + nt * 16 + ((lane >> 4) << 3) + (lane & 7);
                    int gc = kt * 4 + 2 * ks + ((lane >> 3) & 1);
                    ldsm4(b[2 * nt][0], b[2 * nt][1], b[2 * nt + 1][0], b[2 * nt + 1][1],
                          sb + whsw(row, gc));
                }
#pragma unroll
                for (int mi = 0; mi < 2; mi++)
#pragma unroll
                    for (int ni = 0; ni < 4; ni++) MMA_BF16(acc[mi][ni], a[mi], b[ni]);
            }
        }

        // scatter acc -> pre-tile [128][64], stride 65
        const int lr = lane >> 2, lc = lane & 3;
#pragma unroll
        for (int mi = 0; mi < 2; mi++)
#pragma unroll
            for (int ni = 0; ni < 4; ni++) {
                int r = wm * 32 + mi * 16 + lr;
                int cc = wn * 32 + ni * 8 + 2 * lc;
                pre[r * 65 + cc]           = acc[mi][ni][0];
                pre[r * 65 + cc + 1]       = acc[mi][ni][1];
                pre[(r + 8) * 65 + cc]     = acc[mi][ni][2];
                pre[(r + 8) * 65 + cc + 1] = acc[mi][ni][3];
            }
        __syncthreads();

        // fused LSTM elementwise: 8 (b,j) pairs per thread (gx from smem)
#pragma unroll
        for (int s = 0; s < 8; s++) {
            int p = s * 256 + tid;
            int r = p >> 4, jj = p & 15;
            int b = m0 + r;
            float4 gx4 = *(const float4*)&gxs[r * 64 + 4 * jj];
            float p0 = pre[r * 65 + 4 * jj + 0] + gx4.x;
            float p1 = pre[r * 65 + 4 * jj + 1] + gx4.y;
            float p2 = pre[r * 65 + 4 * jj + 2] + gx4.z;
            float p3 = pre[r * 65 + 4 * jj + 3] + gx4.w;
            float ig = sigm(p0);
            float fg = sigm(p1);
            float gg = tanhff(p2);
            float og = sigm(p3);
            float cn = fg * creg[s] + ig * gg;
            creg[s] = cn;
            hout[b * HID + (n0 >> 2) + jj] = __float2bfloat16_rn(og * tanhff(cn));
        }

        // ---- per-m-group grid barrier (64 CTAs; the two groups are independent) ----
        __threadfence();
        __syncthreads();
        if (tid == 0) {
            atomicAdd(&g_barg[grp], 1u);
            unsigned target = (unsigned)(t + 1) * 64u;
            while (*(volatile unsigned*)&g_barg[grp] < target) { }
        }
        __syncthreads();
        __threadfence();
    }

    // ======== fused final FC + log_softmax (after t=127 group barrier) ========
    // Each CTA handles 2 batch rows of its own m-group: b = m0 + 2*bx + {0,1}.
    {
        const __nv_bfloat16* __restrict__ hf = g_h[0];   // t=127 wrote buffer 0
        float* hrow = (float*)(smem + A_OFF);            // 2 x 1024 f32 = 8KB
        float* lg   = (float*)(smem + A_OFF + 8192);     // 2 x 32 logits
        const int bx = blockIdx.x;
#pragma unroll
        for (int rr = 0; rr < 2; rr++) {
            int b = m0 + 2 * bx + rr;
            for (int i = tid; i < HID; i += 256)
                hrow[rr * 1024 + i] = __bfloat162float(hf[(size_t)b * HID + i]);
        }
        __syncthreads();

        // 8 warps x 4 outputs = 32 outputs, each for both rows
#pragma unroll
        for (int rr = 0; rr < 2; rr++) {
#pragma unroll
            for (int oo = 0; oo < 4; oo++) {
                int o = wid * 4 + oo;
                const float* w = wfc + (size_t)o * HID;
                float s = 0.f;
                for (int k = lane; k < HID; k += 32) s += hrow[rr * 1024 + k] * w[k];
#pragma unroll
                for (int off = 16; off; off >>= 1) s += __shfl_xor_sync(0xffffffffu, s, off);
                if (lane == 0) lg[rr * 32 + o] = s;
            }
        }
        __syncthreads();

        if (tid < 64) {                     // warp 0 -> row 0, warp 1 -> row 1
            int rr = tid >> 5, oi = tid & 31;
            float l = lg[rr * 32 + oi];
            float m = l;
#pragma unroll
            for (int off = 16; off; off >>= 1) m = fmaxf(m, __shfl_xor_sync(0xffffffffu, m, off));
            float e = expf(l - m);
            float se = e;
#pragma unroll
            for (int off = 16; off; off >>= 1) se += __shfl_xor_sync(0xffffffffu, se, off);
            out[(m0 + 2 * bx + rr) * NOUT + oi] = l - m - logf(se);
        }
    }
}

// ---------------- launch ----------------
extern "C" void kernel_launch(void* const* d_in, const int* in_sizes, int n_in,
                              void* d_out, int out_size) {
    const float* x    = (const float*)d_in[0];
    const float* w_ii = (const float*)d_in[1];
    const float* w_hi = (const float*)d_in[2];
    const float* b_ii = (const float*)d_in[3];
    const float* b_hi = (const float*)d_in[4];
    const float* w_if = (const float*)d_in[5];
    const float* w_hf = (const float*)d_in[6];
    const float* b_if = (const float*)d_in[7];
    const float* b_hf = (const float*)d_in[8];
    const float* w_io = (const float*)d_in[9];
    const float* w_ho = (const float*)d_in[10];
    const float* b_io = (const float*)d_in[11];
    const float* b_ho = (const float*)d_in[12];
    const float* w_ic = (const float*)d_in[13];
    const float* w_hc = (const float*)d_in[14];
    const float* b_ic = (const float*)d_in[15];
    const float* b_hc = (const float*)d_in[16];
    const float* w_fc = (const float*)d_in[17];

    cudaFuncSetAttribute(k_gemm_x, cudaFuncAttributeMaxDynamicSharedMemorySize, X_SMEM);
    cudaFuncSetAttribute(k_steps,  cudaFuncAttributeMaxDynamicSharedMemorySize, S_SMEM);

    k_prep0<<<2048, 256>>>(x, w_ii, w_if, w_ic, w_io, w_hi, w_hf, w_hc, w_ho);
    k_prep1<<<1024, 256>>>(b_ii, b_hi, b_if, b_hf, b_ic, b_hc, b_io, b_ho);

    k_gemm_x<<<dim3(32, 256), 256, X_SMEM>>>();

    k_steps<<<dim3(64, 2), 256, S_SMEM>>>(w_fc, (float*)d_out);
}